// round 15
// baseline (speedup 1.0000x reference)
#include <cuda_runtime.h>
#include <cuda_bf16.h>
#include <cstdint>

#define NN 20000
#define EE 320000
#define DD 256

// ---------------- scratch (static device globals; no allocation) ----------
__device__ float g_xl[NN * DD];   // h @ Wl
__device__ float g_xr[NN * DD];   // h @ Wr
__device__ __nv_bfloat16 g_Ah[NN * DD];  // current layer input, bf16 hi
__device__ __nv_bfloat16 g_Al[NN * DD];  // current layer input, bf16 lo
__device__ int   g_deg[NN];       // zero-initialized; re-zeroed by scan_kernel
__device__ int   g_rowptr[NN + 1];
__device__ int   g_wptr[NN];
__device__ int   g_col[EE];       // src indices sorted by dst (CSR)

// transposed, bf16-split weights for all layers: [2*layer + (0=Wl,1=Wr)]
__device__ __nv_bfloat16 g_Bh[8][DD * DD];
__device__ __nv_bfloat16 g_Bl[8][DD * DD];

// ---------------- helpers ---------------------------------------------------
__device__ __forceinline__ uint32_t smem_u32(const void* p) {
    uint32_t a;
    asm("{ .reg .u64 t; cvta.to.shared.u64 t, %1; cvt.u32.u64 %0, t; }"
        : "=r"(a) : "l"(p));
    return a;
}
#define SWZ(o) ((o) ^ (((o) >> 3) & 0x70))

#define LDSM_X4(r0, r1, r2, r3, a)                                          \
    asm volatile("ldmatrix.sync.aligned.m8n8.x4.shared.b16 {%0,%1,%2,%3}, [%4];" \
                 : "=r"(r0), "=r"(r1), "=r"(r2), "=r"(r3) : "r"(a))

#define MMA_BF16(d, a, b)                                                   \
    asm volatile("mma.sync.aligned.m16n8k16.row.col.f32.bf16.bf16.f32 "     \
                 "{%0,%1,%2,%3}, {%4,%5,%6,%7}, {%8,%9}, {%0,%1,%2,%3};"    \
                 : "+f"((d)[0]), "+f"((d)[1]), "+f"((d)[2]), "+f"((d)[3])   \
                 : "r"((a)[0]), "r"((a)[1]), "r"((a)[2]), "r"((a)[3]),      \
                   "r"((b)[0]), "r"((b)[1]))

#define CP_ASYNC16(dst, src)                                                \
    asm volatile("cp.async.cg.shared.global [%0], [%1], 16;"                \
                 :: "r"(dst), "l"(src) : "memory")
#define CP_ASYNC16Z(dst, src, sz)                                           \
    asm volatile("cp.async.cg.shared.global [%0], [%1], 16, %2;"            \
                 :: "r"(dst), "l"(src), "r"(sz) : "memory")
#define CP_COMMIT() asm volatile("cp.async.commit_group;" ::: "memory")
#define CP_WAIT(n)  asm volatile("cp.async.wait_group %0;" :: "n"(n) : "memory")

// ---------------- CSR build ----------------------------------------------
__global__ void hist_kernel(const int* __restrict__ ei, int E) {
    int e = blockIdx.x * blockDim.x + threadIdx.x;
    if (e < E) atomicAdd(&g_deg[ei[E + e]], 1);
}

__global__ void scan_kernel(int n) {
    __shared__ int wsum[32];
    __shared__ int carry;
    int t = threadIdx.x, lane = t & 31, w = t >> 5;
    if (t == 0) { carry = 0; g_rowptr[0] = 0; }
    __syncthreads();
    for (int base = 0; base < n; base += 1024) {
        int i = base + t;
        int v = (i < n) ? g_deg[i] : 0;
        if (i < n) g_deg[i] = 0;
        int s = v;
#pragma unroll
        for (int off = 1; off < 32; off <<= 1) {
            int u = __shfl_up_sync(0xffffffffu, s, off);
            if (lane >= off) s += u;
        }
        if (lane == 31) wsum[w] = s;
        __syncthreads();
        if (w == 0) {
            int ws = wsum[lane];
#pragma unroll
            for (int off = 1; off < 32; off <<= 1) {
                int u = __shfl_up_sync(0xffffffffu, ws, off);
                if (lane >= off) ws += u;
            }
            wsum[lane] = ws;
        }
        __syncthreads();
        int incl = s + (w ? wsum[w - 1] : 0) + carry;
        if (i < n) {
            g_rowptr[i + 1] = incl;
            g_wptr[i]       = incl - v;
        }
        __syncthreads();
        if (t == 1023) carry = incl;
        __syncthreads();
    }
}

__global__ void scatter_kernel(const int* __restrict__ ei, int E) {
    int e = blockIdx.x * blockDim.x + threadIdx.x;
    if (e < E) {
        int dst = ei[E + e];
        int pos = atomicAdd(&g_wptr[dst], 1);
        g_col[pos] = ei[e];
    }
}

// ---------------- x -> bf16 hi/lo split (layer 0 input) --------------------
__global__ void convert_x_kernel(const float* __restrict__ x, int total4) {
    int i = blockIdx.x * blockDim.x + threadIdx.x;
    if (i >= total4) return;
    float4 v = ((const float4*)x)[i];
    __nv_bfloat16 h0 = __float2bfloat16_rn(v.x);
    __nv_bfloat16 h1 = __float2bfloat16_rn(v.y);
    __nv_bfloat16 h2 = __float2bfloat16_rn(v.z);
    __nv_bfloat16 h3 = __float2bfloat16_rn(v.w);
    __nv_bfloat16 l0 = __float2bfloat16_rn(v.x - __bfloat162float(h0));
    __nv_bfloat16 l1 = __float2bfloat16_rn(v.y - __bfloat162float(h1));
    __nv_bfloat16 l2 = __float2bfloat16_rn(v.z - __bfloat162float(h2));
    __nv_bfloat16 l3 = __float2bfloat16_rn(v.w - __bfloat162float(h3));
    uint2 hp, lp;
    hp.x = (uint32_t)__bfloat16_as_ushort(h0) | ((uint32_t)__bfloat16_as_ushort(h1) << 16);
    hp.y = (uint32_t)__bfloat16_as_ushort(h2) | ((uint32_t)__bfloat16_as_ushort(h3) << 16);
    lp.x = (uint32_t)__bfloat16_as_ushort(l0) | ((uint32_t)__bfloat16_as_ushort(l1) << 16);
    lp.y = (uint32_t)__bfloat16_as_ushort(l2) | ((uint32_t)__bfloat16_as_ushort(l3) << 16);
    ((uint2*)g_Ah)[i] = hp;
    ((uint2*)g_Al)[i] = lp;
}

// ---------------- weight transpose + bf16 hi/lo split (all 8 matrices) -----
__global__ void prep_all_kernel(const float* W0, const float* W1,
                                const float* W2, const float* W3,
                                const float* W4, const float* W5,
                                const float* W6, const float* W7) {
    __shared__ float t[32][33];
    const float* sel[8] = {W0, W1, W2, W3, W4, W5, W6, W7};
    int z = blockIdx.z;
    const float* W = sel[z];
    __nv_bfloat16* Oh = g_Bh[z];
    __nv_bfloat16* Ol = g_Bl[z];
    int bx = blockIdx.x * 32, by = blockIdx.y * 32;
    int tx = threadIdx.x, ty = threadIdx.y;       // 32 x 8
#pragma unroll
    for (int i = 0; i < 32; i += 8)
        t[ty + i][tx] = W[(by + ty + i) * DD + bx + tx];
    __syncthreads();
#pragma unroll
    for (int i = 0; i < 32; i += 8) {
        float v = t[tx][ty + i];
        __nv_bfloat16 h = __float2bfloat16_rn(v);
        __nv_bfloat16 l = __float2bfloat16_rn(v - __bfloat162float(h));
        int n = bx + ty + i, k = by + tx;
        Oh[n * DD + k] = h;
        Ol[n * DD + k] = l;
    }
}

// ---------------- pure-bf16 mma.sync GEMM, 64x128 tile, 2 CTAs/SM ----------
// (R12 configuration — best measured GEMM: 42 us, tensor 62%)
#define ST_AH 0
#define ST_AL 8192
#define ST_BH 16384
#define ST_BL 32768
#define STAGE 49152
#define GEMM_SMEM 98304

__global__ void __launch_bounds__(256, 2)
gemm_kernel(int M, int layer) {
    extern __shared__ char smem[];
    uint32_t sb = smem_u32(smem);

    int tid = threadIdx.x;
    int lane = tid & 31, wid = tid >> 5;
    int warpM = wid >> 2, warpN = wid & 3;   // 2 x 4
    int rowBase = blockIdx.y << 6;           // 64 rows per CTA
    int colBase = blockIdx.x << 7;           // 0..511 in steps of 128

    int widx = layer * 2 + (colBase >= 256 ? 1 : 0);
    const __nv_bfloat16* __restrict__ Bh = g_Bh[widx];
    const __nv_bfloat16* __restrict__ Bl = g_Bl[widx];
    int nBase = colBase & 255;

    float acc[2][4][4];
#pragma unroll
    for (int i = 0; i < 2; i++)
#pragma unroll
        for (int j = 0; j < 4; j++)
#pragma unroll
            for (int q = 0; q < 4; q++) acc[i][j][q] = 0.f;

    uint32_t aOff[2], bOff[2];
#pragma unroll
    for (int im = 0; im < 2; im++)
        aOff[im] = (uint32_t)((warpM * 32 + im * 16 + (lane & 15)) * 128 +
                              (lane >> 4) * 16);
#pragma unroll
    for (int ip = 0; ip < 2; ip++)
        bOff[ip] = (uint32_t)((warpN * 32 + ip * 16 + ((lane >> 4) & 1) * 8 +
                               (lane & 7)) * 128 + ((lane >> 3) & 1) * 16);

    int seg = tid & 7;                       // 16B segment along 128B row
    int r0t = tid >> 3;                      // 0..31

    auto issue = [&](int ch) {
        uint32_t base = sb + (uint32_t)(ch & 1) * STAGE;
        int k0 = ch << 6;
#pragma unroll
        for (int it = 0; it < 2; it++) {
            int r = r0t + it * 32;
            uint32_t dsw = SWZ((uint32_t)(r * 128 + 16 * seg));
            int row = rowBase + r;
            uint32_t sz = (row < M) ? 16u : 0u;
            const __nv_bfloat16* pa = &g_Ah[(size_t)row * DD + k0 + 8 * seg];
            const __nv_bfloat16* pl = &g_Al[(size_t)row * DD + k0 + 8 * seg];
            if (row >= M) { pa = g_Ah; pl = g_Al; }
            CP_ASYNC16Z(base + ST_AH + dsw, pa, sz);
            CP_ASYNC16Z(base + ST_AL + dsw, pl, sz);
        }
#pragma unroll
        for (int it = 0; it < 4; it++) {
            int r = r0t + it * 32;
            uint32_t dsw = SWZ((uint32_t)(r * 128 + 16 * seg));
            CP_ASYNC16(base + ST_BH + dsw, &Bh[(nBase + r) * DD + k0 + 8 * seg]);
            CP_ASYNC16(base + ST_BL + dsw, &Bl[(nBase + r) * DD + k0 + 8 * seg]);
        }
        CP_COMMIT();
    };

    issue(0);
    issue(1);

#pragma unroll
    for (int ch = 0; ch < 4; ch++) {
        if (ch < 3) { CP_WAIT(1); } else { CP_WAIT(0); }
        __syncthreads();

        uint32_t base = sb + (uint32_t)(ch & 1) * STAGE;
#pragma unroll
        for (int kk = 0; kk < 4; kk++) {
            uint32_t kb = (uint32_t)(kk * 32);
            uint32_t aH[2][4], aL[2][4], bH[4][2], bL[4][2];
#pragma unroll
            for (int im = 0; im < 2; im++) {
                LDSM_X4(aH[im][0], aH[im][1], aH[im][2], aH[im][3],
                        base + ST_AH + SWZ(aOff[im] + kb));
                LDSM_X4(aL[im][0], aL[im][1], aL[im][2], aL[im][3],
                        base + ST_AL + SWZ(aOff[im] + kb));
            }
#pragma unroll
            for (int ip = 0; ip < 2; ip++) {
                LDSM_X4(bH[2 * ip][0], bH[2 * ip][1],
                        bH[2 * ip + 1][0], bH[2 * ip + 1][1],
                        base + ST_BH + SWZ(bOff[ip] + kb));
                LDSM_X4(bL[2 * ip][0], bL[2 * ip][1],
                        bL[2 * ip + 1][0], bL[2 * ip + 1][1],
                        base + ST_BL + SWZ(bOff[ip] + kb));
            }
#pragma unroll
            for (int im = 0; im < 2; im++)
#pragma unroll
                for (int jn = 0; jn < 4; jn++) {
                    MMA_BF16(acc[im][jn], aH[im], bH[jn]);
                    MMA_BF16(acc[im][jn], aH[im], bL[jn]);
                    MMA_BF16(acc[im][jn], aL[im], bH[jn]);
                }
        }
        __syncthreads();
        if (ch + 2 < 4) issue(ch + 2);
    }

    float* __restrict__ out = (colBase < 256) ? g_xl : g_xr;
    int cBase = nBase + warpN * 32;
#pragma unroll
    for (int im = 0; im < 2; im++) {
        int r0 = rowBase + warpM * 32 + im * 16 + (lane >> 2);
#pragma unroll
        for (int jn = 0; jn < 4; jn++) {
            int c = cBase + jn * 8 + (lane & 3) * 2;
            if (r0 < M)
                *(float2*)&out[r0 * DD + c] =
                    make_float2(acc[im][jn][0], acc[im][jn][1]);
            if (r0 + 8 < M)
                *(float2*)&out[(r0 + 8) * DD + c] =
                    make_float2(acc[im][jn][2], acc[im][jn][3]);
        }
    }
}

// ---------------- fused GATv2 aggregate + bias + LayerNorm + ReLU ---------
// Block = ONE node, 64 threads (2 warps). Lane owns 4 channels (float4).
// ALL edges processed in masked 8-wide batches: the remainder is padded with
// the batch's first edge and its post-reduction score forced to -1e30
// (p = 0, exact zero contribution) — no serial tail.
__device__ __forceinline__ float4 lrelu4(float4 a) {
    a.x = (a.x > 0.f) ? a.x : 0.2f * a.x;
    a.y = (a.y > 0.f) ? a.y : 0.2f * a.y;
    a.z = (a.z > 0.f) ? a.z : 0.2f * a.z;
    a.w = (a.w > 0.f) ? a.w : 0.2f * a.w;
    return a;
}
__device__ __forceinline__ float dot4(float4 a, float4 b) {
    return a.x * b.x + a.y * b.y + a.z * b.z + a.w * b.w;
}
__device__ __forceinline__ float segred16(float s) {
#pragma unroll
    for (int off = 8; off; off >>= 1)
        s += __shfl_xor_sync(0xffffffffu, s, off);
    return s;
}

__global__ void __launch_bounds__(64)
gat_agg_kernel(const float* __restrict__ att, const float* __restrict__ bias,
               const float* __restrict__ gamma, const float* __restrict__ beta,
               float* __restrict__ ext_out, int write_ext) {
    int node = blockIdx.x;
    int warp = threadIdx.x >> 5;                      // 0..1
    int lane = threadIdx.x & 31;
    int c0   = (warp * 2 + (lane >> 4)) * 64 + (lane & 15) * 4;

    float4 xrv  = *(const float4*)&g_xr[(size_t)node * DD + c0];
    float4 attv = *(const float4*)&att[c0];

    // self loop initializes running softmax state (p = 1)
    float4 xs = *(const float4*)&g_xl[(size_t)node * DD + c0];
    float4 a = lrelu4(make_float4(xs.x + xrv.x, xs.y + xrv.y,
                                  xs.z + xrv.z, xs.w + xrv.w));
    float m = segred16(dot4(a, attv));
    float lsum = 1.f;
    float4 acc = xs;

    int e   = g_rowptr[node];
    int end = g_rowptr[node + 1];

    for (; e < end; e += 8) {
        int cnt = end - e;                 // >= 1
        if (cnt > 8) cnt = 8;
        int idx[8];
#pragma unroll
        for (int j = 0; j < 8; j++)
            idx[j] = g_col[e + ((j < cnt) ? j : 0)];
        float4 xv[8];
#pragma unroll
        for (int j = 0; j < 8; j++)
            xv[j] = *(const float4*)&g_xl[(size_t)idx[j] * DD + c0];
        float sv[8];
#pragma unroll
        for (int j = 0; j < 8; j++) {
            float4 aj = lrelu4(make_float4(xv[j].x + xrv.x, xv[j].y + xrv.y,
                                           xv[j].z + xrv.z, xv[j].w + xrv.w));
            sv[j] = dot4(aj, attv);
        }
#pragma unroll
        for (int off = 8; off; off >>= 1)
#pragma unroll
            for (int j = 0; j < 8; j++)
                sv[j] += __shfl_xor_sync(0xffffffffu, sv[j], off);
#pragma unroll
        for (int j = 0; j < 8; j++)
            if (j >= cnt) sv[j] = -1e30f;   // padded lanes contribute zero
        float nm = m;
#pragma unroll
        for (int j = 0; j < 8; j++) nm = fmaxf(nm, sv[j]);
        float sc = __expf(m - nm);
        float p[8];
#pragma unroll
        for (int j = 0; j < 8; j++) p[j] = __expf(sv[j] - nm);
        acc.x *= sc; acc.y *= sc; acc.z *= sc; acc.w *= sc;
        lsum *= sc;
#pragma unroll
        for (int j = 0; j < 8; j++) {
            acc.x += p[j] * xv[j].x;
            acc.y += p[j] * xv[j].y;
            acc.z += p[j] * xv[j].z;
            acc.w += p[j] * xv[j].w;
            lsum += p[j];
        }
        m = nm;
    }

    float inv_l = 1.0f / lsum;
    float4 ox4;
    ox4.x = acc.x * inv_l + bias[c0];
    ox4.y = acc.y * inv_l + bias[c0 + 1];
    ox4.z = acc.z * inv_l + bias[c0 + 2];
    ox4.w = acc.w * inv_l + bias[c0 + 3];

    float s1r = ox4.x + ox4.y + ox4.z + ox4.w;
    float s2r = ox4.x * ox4.x + ox4.y * ox4.y + ox4.z * ox4.z + ox4.w * ox4.w;
#pragma unroll
    for (int off = 16; off; off >>= 1) {
        s1r += __shfl_xor_sync(0xffffffffu, s1r, off);
        s2r += __shfl_xor_sync(0xffffffffu, s2r, off);
    }
    __shared__ float sh1[2], sh2[2];
    if (lane == 0) { sh1[warp] = s1r; sh2[warp] = s2r; }
    __syncthreads();
    s1r = sh1[0] + sh1[1];
    s2r = sh2[0] + sh2[1];

    float mean = s1r * (1.0f / DD);
    float var  = s2r * (1.0f / DD) - mean * mean;
    float rinv = rsqrtf(var + 1e-5f);

    float o0 = fmaxf((ox4.x - mean) * rinv * gamma[c0]     + beta[c0],     0.f);
    float o1 = fmaxf((ox4.y - mean) * rinv * gamma[c0 + 1] + beta[c0 + 1], 0.f);
    float o2 = fmaxf((ox4.z - mean) * rinv * gamma[c0 + 2] + beta[c0 + 2], 0.f);
    float o3 = fmaxf((ox4.w - mean) * rinv * gamma[c0 + 3] + beta[c0 + 3], 0.f);

    if (write_ext) {
        *(float4*)&ext_out[(size_t)node * DD + c0] = make_float4(o0, o1, o2, o3);
    } else {
        __nv_bfloat16 h0 = __float2bfloat16_rn(o0);
        __nv_bfloat16 h1 = __float2bfloat16_rn(o1);
        __nv_bfloat16 h2 = __float2bfloat16_rn(o2);
        __nv_bfloat16 h3 = __float2bfloat16_rn(o3);
        __nv_bfloat16 l0 = __float2bfloat16_rn(o0 - __bfloat162float(h0));
        __nv_bfloat16 l1 = __float2bfloat16_rn(o1 - __bfloat162float(h1));
        __nv_bfloat16 l2 = __float2bfloat16_rn(o2 - __bfloat162float(h2));
        __nv_bfloat16 l3 = __float2bfloat16_rn(o3 - __bfloat162float(h3));
        uint2 hp, lp;
        hp.x = (uint32_t)__bfloat16_as_ushort(h0) |
               ((uint32_t)__bfloat16_as_ushort(h1) << 16);
        hp.y = (uint32_t)__bfloat16_as_ushort(h2) |
               ((uint32_t)__bfloat16_as_ushort(h3) << 16);
        lp.x = (uint32_t)__bfloat16_as_ushort(l0) |
               ((uint32_t)__bfloat16_as_ushort(l1) << 16);
        lp.y = (uint32_t)__bfloat16_as_ushort(l2) |
               ((uint32_t)__bfloat16_as_ushort(l3) << 16);
        *(uint2*)&g_Ah[(size_t)node * DD + c0] = hp;
        *(uint2*)&g_Al[(size_t)node * DD + c0] = lp;
    }
}

// ---------------- launch ---------------------------------------------------
extern "C" void kernel_launch(void* const* d_in, const int* in_sizes, int n_in,
                              void* d_out, int out_size) {
    const float* x  = (const float*)d_in[0];
    const int*   ei = (const int*)d_in[1];
    int E = in_sizes[1] / 2;          // 320000
    int N = in_sizes[0] / DD;         // 20000
    float* out = (float*)d_out;

    static int inited = 0;
    static cudaStream_t s2;
    static cudaEvent_t evFork, evJoin;
    if (!inited) {
        cudaFuncSetAttribute(gemm_kernel,
                             cudaFuncAttributeMaxDynamicSharedMemorySize,
                             GEMM_SMEM);
        cudaStreamCreateWithFlags(&s2, cudaStreamNonBlocking);
        cudaEventCreateWithFlags(&evFork, cudaEventDisableTiming);
        cudaEventCreateWithFlags(&evJoin, cudaEventDisableTiming);
        inited = 1;
    }
    dim3 ggrid(4, (N + 63) / 64);
    int total4 = N * DD / 4;

    // Fork: CSR chain (hist->scan->scatter) on s2, concurrent with the
    // dense chain (convert->prep->gemm0) on the main stream. Join before agg0.
    cudaEventRecord(evFork, 0);
    cudaStreamWaitEvent(s2, evFork, 0);

    convert_x_kernel<<<(total4 + 255) / 256, 256>>>(x, total4);       // idx 0
    prep_all_kernel<<<dim3(8, 8, 8), dim3(32, 8)>>>(                  // idx 1
        (const float*)d_in[2],  (const float*)d_in[3],
        (const float*)d_in[8],  (const float*)d_in[9],
        (const float*)d_in[14], (const float*)d_in[15],
        (const float*)d_in[20], (const float*)d_in[21]);
    hist_kernel<<<(E + 255) / 256, 256, 0, s2>>>(ei, E);              // idx 2
    gemm_kernel<<<ggrid, 256, GEMM_SMEM>>>(N, 0);                     // idx 3 <- profiled
    scan_kernel<<<1, 1024, 0, s2>>>(N);                               // idx 4
    scatter_kernel<<<(E + 255) / 256, 256, 0, s2>>>(ei, E);           // idx 5

    cudaEventRecord(evJoin, s2);
    cudaStreamWaitEvent(0, evJoin, 0);

    for (int layer = 0; layer < 4; layer++) {
        const float* att = (const float*)d_in[2 + 6 * layer + 2];
        const float* b   = (const float*)d_in[2 + 6 * layer + 3];
        const float* g   = (const float*)d_in[2 + 6 * layer + 4];
        const float* be  = (const float*)d_in[2 + 6 * layer + 5];

        if (layer > 0)
            gemm_kernel<<<ggrid, 256, GEMM_SMEM>>>(N, layer);
        gat_agg_kernel<<<N, 64>>>(att, b, g, be, out, layer == 3);
    }
}

// round 16
// speedup vs baseline: 1.5882x; 1.5882x over previous
#include <cuda_runtime.h>
#include <cuda_bf16.h>
#include <cstdint>

#define NN 20000
#define EE 320000
#define DD 256

// ---------------- scratch (static device globals; no allocation) ----------
__device__ float g_xl[NN * DD];   // h @ Wl
__device__ float g_xr[NN * DD];   // h @ Wr
__device__ __nv_bfloat16 g_Ah[NN * DD];  // current layer input, bf16 hi
__device__ __nv_bfloat16 g_Al[NN * DD];  // current layer input, bf16 lo
__device__ int   g_deg[NN];       // zero-initialized; re-zeroed by scan_kernel
__device__ int   g_rowptr[NN + 1];
__device__ int   g_wptr[NN];
__device__ int   g_col[EE];       // src indices sorted by dst (CSR)

// transposed, bf16-split weights for all layers: [2*layer + (0=Wl,1=Wr)]
__device__ __nv_bfloat16 g_Bh[8][DD * DD];
__device__ __nv_bfloat16 g_Bl[8][DD * DD];

// ---------------- helpers ---------------------------------------------------
__device__ __forceinline__ uint32_t smem_u32(const void* p) {
    uint32_t a;
    asm("{ .reg .u64 t; cvta.to.shared.u64 t, %1; cvt.u32.u64 %0, t; }"
        : "=r"(a) : "l"(p));
    return a;
}
#define SWZ(o) ((o) ^ (((o) >> 3) & 0x70))

#define LDSM_X4(r0, r1, r2, r3, a)                                          \
    asm volatile("ldmatrix.sync.aligned.m8n8.x4.shared.b16 {%0,%1,%2,%3}, [%4];" \
                 : "=r"(r0), "=r"(r1), "=r"(r2), "=r"(r3) : "r"(a))

#define MMA_BF16(d, a, b)                                                   \
    asm volatile("mma.sync.aligned.m16n8k16.row.col.f32.bf16.bf16.f32 "     \
                 "{%0,%1,%2,%3}, {%4,%5,%6,%7}, {%8,%9}, {%0,%1,%2,%3};"    \
                 : "+f"((d)[0]), "+f"((d)[1]), "+f"((d)[2]), "+f"((d)[3])   \
                 : "r"((a)[0]), "r"((a)[1]), "r"((a)[2]), "r"((a)[3]),      \
                   "r"((b)[0]), "r"((b)[1]))

#define CP_ASYNC16(dst, src)                                                \
    asm volatile("cp.async.cg.shared.global [%0], [%1], 16;"                \
                 :: "r"(dst), "l"(src) : "memory")
#define CP_ASYNC16Z(dst, src, sz)                                           \
    asm volatile("cp.async.cg.shared.global [%0], [%1], 16, %2;"            \
                 :: "r"(dst), "l"(src), "r"(sz) : "memory")
#define CP_COMMIT() asm volatile("cp.async.commit_group;" ::: "memory")
#define CP_WAIT(n)  asm volatile("cp.async.wait_group %0;" :: "n"(n) : "memory")

// ---------------- CSR build ----------------------------------------------
__global__ void hist_kernel(const int* __restrict__ ei, int E) {
    int e = blockIdx.x * blockDim.x + threadIdx.x;
    if (e < E) atomicAdd(&g_deg[ei[E + e]], 1);
}

__global__ void scan_kernel(int n) {
    __shared__ int wsum[32];
    __shared__ int carry;
    int t = threadIdx.x, lane = t & 31, w = t >> 5;
    if (t == 0) { carry = 0; g_rowptr[0] = 0; }
    __syncthreads();
    for (int base = 0; base < n; base += 1024) {
        int i = base + t;
        int v = (i < n) ? g_deg[i] : 0;
        if (i < n) g_deg[i] = 0;
        int s = v;
#pragma unroll
        for (int off = 1; off < 32; off <<= 1) {
            int u = __shfl_up_sync(0xffffffffu, s, off);
            if (lane >= off) s += u;
        }
        if (lane == 31) wsum[w] = s;
        __syncthreads();
        if (w == 0) {
            int ws = wsum[lane];
#pragma unroll
            for (int off = 1; off < 32; off <<= 1) {
                int u = __shfl_up_sync(0xffffffffu, ws, off);
                if (lane >= off) ws += u;
            }
            wsum[lane] = ws;
        }
        __syncthreads();
        int incl = s + (w ? wsum[w - 1] : 0) + carry;
        if (i < n) {
            g_rowptr[i + 1] = incl;
            g_wptr[i]       = incl - v;
        }
        __syncthreads();
        if (t == 1023) carry = incl;
        __syncthreads();
    }
}

__global__ void scatter_kernel(const int* __restrict__ ei, int E) {
    int e = blockIdx.x * blockDim.x + threadIdx.x;
    if (e < E) {
        int dst = ei[E + e];
        int pos = atomicAdd(&g_wptr[dst], 1);
        g_col[pos] = ei[e];
    }
}

// ---------------- x -> bf16 hi/lo split (layer 0 input) --------------------
__global__ void convert_x_kernel(const float* __restrict__ x, int total4) {
    int i = blockIdx.x * blockDim.x + threadIdx.x;
    if (i >= total4) return;
    float4 v = ((const float4*)x)[i];
    __nv_bfloat16 h0 = __float2bfloat16_rn(v.x);
    __nv_bfloat16 h1 = __float2bfloat16_rn(v.y);
    __nv_bfloat16 h2 = __float2bfloat16_rn(v.z);
    __nv_bfloat16 h3 = __float2bfloat16_rn(v.w);
    __nv_bfloat16 l0 = __float2bfloat16_rn(v.x - __bfloat162float(h0));
    __nv_bfloat16 l1 = __float2bfloat16_rn(v.y - __bfloat162float(h1));
    __nv_bfloat16 l2 = __float2bfloat16_rn(v.z - __bfloat162float(h2));
    __nv_bfloat16 l3 = __float2bfloat16_rn(v.w - __bfloat162float(h3));
    uint2 hp, lp;
    hp.x = (uint32_t)__bfloat16_as_ushort(h0) | ((uint32_t)__bfloat16_as_ushort(h1) << 16);
    hp.y = (uint32_t)__bfloat16_as_ushort(h2) | ((uint32_t)__bfloat16_as_ushort(h3) << 16);
    lp.x = (uint32_t)__bfloat16_as_ushort(l0) | ((uint32_t)__bfloat16_as_ushort(l1) << 16);
    lp.y = (uint32_t)__bfloat16_as_ushort(l2) | ((uint32_t)__bfloat16_as_ushort(l3) << 16);
    ((uint2*)g_Ah)[i] = hp;
    ((uint2*)g_Al)[i] = lp;
}

// ---------------- weight transpose + bf16 hi/lo split (all 8 matrices) -----
__global__ void prep_all_kernel(const float* W0, const float* W1,
                                const float* W2, const float* W3,
                                const float* W4, const float* W5,
                                const float* W6, const float* W7) {
    __shared__ float t[32][33];
    const float* sel[8] = {W0, W1, W2, W3, W4, W5, W6, W7};
    int z = blockIdx.z;
    const float* W = sel[z];
    __nv_bfloat16* Oh = g_Bh[z];
    __nv_bfloat16* Ol = g_Bl[z];
    int bx = blockIdx.x * 32, by = blockIdx.y * 32;
    int tx = threadIdx.x, ty = threadIdx.y;       // 32 x 8
#pragma unroll
    for (int i = 0; i < 32; i += 8)
        t[ty + i][tx] = W[(by + ty + i) * DD + bx + tx];
    __syncthreads();
#pragma unroll
    for (int i = 0; i < 32; i += 8) {
        float v = t[tx][ty + i];
        __nv_bfloat16 h = __float2bfloat16_rn(v);
        __nv_bfloat16 l = __float2bfloat16_rn(v - __bfloat162float(h));
        int n = bx + ty + i, k = by + tx;
        Oh[n * DD + k] = h;
        Ol[n * DD + k] = l;
    }
}

// ---------------- pure-bf16 mma.sync GEMM, 64x128 tile, 2 CTAs/SM ----------
// (R12 configuration — best measured GEMM: 42 us @ full clock)
#define ST_AH 0
#define ST_AL 8192
#define ST_BH 16384
#define ST_BL 32768
#define STAGE 49152
#define GEMM_SMEM 98304

__global__ void __launch_bounds__(256, 2)
gemm_kernel(int M, int layer) {
    extern __shared__ char smem[];
    uint32_t sb = smem_u32(smem);

    int tid = threadIdx.x;
    int lane = tid & 31, wid = tid >> 5;
    int warpM = wid >> 2, warpN = wid & 3;   // 2 x 4
    int rowBase = blockIdx.y << 6;           // 64 rows per CTA
    int colBase = blockIdx.x << 7;           // 0..511 in steps of 128

    int widx = layer * 2 + (colBase >= 256 ? 1 : 0);
    const __nv_bfloat16* __restrict__ Bh = g_Bh[widx];
    const __nv_bfloat16* __restrict__ Bl = g_Bl[widx];
    int nBase = colBase & 255;

    float acc[2][4][4];
#pragma unroll
    for (int i = 0; i < 2; i++)
#pragma unroll
        for (int j = 0; j < 4; j++)
#pragma unroll
            for (int q = 0; q < 4; q++) acc[i][j][q] = 0.f;

    uint32_t aOff[2], bOff[2];
#pragma unroll
    for (int im = 0; im < 2; im++)
        aOff[im] = (uint32_t)((warpM * 32 + im * 16 + (lane & 15)) * 128 +
                              (lane >> 4) * 16);
#pragma unroll
    for (int ip = 0; ip < 2; ip++)
        bOff[ip] = (uint32_t)((warpN * 32 + ip * 16 + ((lane >> 4) & 1) * 8 +
                               (lane & 7)) * 128 + ((lane >> 3) & 1) * 16);

    int seg = tid & 7;                       // 16B segment along 128B row
    int r0t = tid >> 3;                      // 0..31

    auto issue = [&](int ch) {
        uint32_t base = sb + (uint32_t)(ch & 1) * STAGE;
        int k0 = ch << 6;
#pragma unroll
        for (int it = 0; it < 2; it++) {
            int r = r0t + it * 32;
            uint32_t dsw = SWZ((uint32_t)(r * 128 + 16 * seg));
            int row = rowBase + r;
            uint32_t sz = (row < M) ? 16u : 0u;
            const __nv_bfloat16* pa = &g_Ah[(size_t)row * DD + k0 + 8 * seg];
            const __nv_bfloat16* pl = &g_Al[(size_t)row * DD + k0 + 8 * seg];
            if (row >= M) { pa = g_Ah; pl = g_Al; }
            CP_ASYNC16Z(base + ST_AH + dsw, pa, sz);
            CP_ASYNC16Z(base + ST_AL + dsw, pl, sz);
        }
#pragma unroll
        for (int it = 0; it < 4; it++) {
            int r = r0t + it * 32;
            uint32_t dsw = SWZ((uint32_t)(r * 128 + 16 * seg));
            CP_ASYNC16(base + ST_BH + dsw, &Bh[(nBase + r) * DD + k0 + 8 * seg]);
            CP_ASYNC16(base + ST_BL + dsw, &Bl[(nBase + r) * DD + k0 + 8 * seg]);
        }
        CP_COMMIT();
    };

    issue(0);
    issue(1);

#pragma unroll
    for (int ch = 0; ch < 4; ch++) {
        if (ch < 3) { CP_WAIT(1); } else { CP_WAIT(0); }
        __syncthreads();

        uint32_t base = sb + (uint32_t)(ch & 1) * STAGE;
#pragma unroll
        for (int kk = 0; kk < 4; kk++) {
            uint32_t kb = (uint32_t)(kk * 32);
            uint32_t aH[2][4], aL[2][4], bH[4][2], bL[4][2];
#pragma unroll
            for (int im = 0; im < 2; im++) {
                LDSM_X4(aH[im][0], aH[im][1], aH[im][2], aH[im][3],
                        base + ST_AH + SWZ(aOff[im] + kb));
                LDSM_X4(aL[im][0], aL[im][1], aL[im][2], aL[im][3],
                        base + ST_AL + SWZ(aOff[im] + kb));
            }
#pragma unroll
            for (int ip = 0; ip < 2; ip++) {
                LDSM_X4(bH[2 * ip][0], bH[2 * ip][1],
                        bH[2 * ip + 1][0], bH[2 * ip + 1][1],
                        base + ST_BH + SWZ(bOff[ip] + kb));
                LDSM_X4(bL[2 * ip][0], bL[2 * ip][1],
                        bL[2 * ip + 1][0], bL[2 * ip + 1][1],
                        base + ST_BL + SWZ(bOff[ip] + kb));
            }
#pragma unroll
            for (int im = 0; im < 2; im++)
#pragma unroll
                for (int jn = 0; jn < 4; jn++) {
                    MMA_BF16(acc[im][jn], aH[im], bH[jn]);
                    MMA_BF16(acc[im][jn], aH[im], bL[jn]);
                    MMA_BF16(acc[im][jn], aL[im], bH[jn]);
                }
        }
        __syncthreads();
        if (ch + 2 < 4) issue(ch + 2);
    }

    float* __restrict__ out = (colBase < 256) ? g_xl : g_xr;
    int cBase = nBase + warpN * 32;
#pragma unroll
    for (int im = 0; im < 2; im++) {
        int r0 = rowBase + warpM * 32 + im * 16 + (lane >> 2);
#pragma unroll
        for (int jn = 0; jn < 4; jn++) {
            int c = cBase + jn * 8 + (lane & 3) * 2;
            if (r0 < M)
                *(float2*)&out[r0 * DD + c] =
                    make_float2(acc[im][jn][0], acc[im][jn][1]);
            if (r0 + 8 < M)
                *(float2*)&out[(r0 + 8) * DD + c] =
                    make_float2(acc[im][jn][2], acc[im][jn][3]);
        }
    }
}

// ---------------- fused GATv2 aggregate + bias + LayerNorm + ReLU ---------
// Block = ONE node, 64 threads (2 warps). Lane owns 4 channels (float4).
// Full 8-wide batches run unmasked (hot path identical to R13); ONE final
// masked batch handles the remainder (padded with the batch's first edge,
// padded scores forced to -1e30 after reduction -> p = 0 exactly).
__device__ __forceinline__ float4 lrelu4(float4 a) {
    a.x = (a.x > 0.f) ? a.x : 0.2f * a.x;
    a.y = (a.y > 0.f) ? a.y : 0.2f * a.y;
    a.z = (a.z > 0.f) ? a.z : 0.2f * a.z;
    a.w = (a.w > 0.f) ? a.w : 0.2f * a.w;
    return a;
}
__device__ __forceinline__ float dot4(float4 a, float4 b) {
    return a.x * b.x + a.y * b.y + a.z * b.z + a.w * b.w;
}
__device__ __forceinline__ float segred16(float s) {
#pragma unroll
    for (int off = 8; off; off >>= 1)
        s += __shfl_xor_sync(0xffffffffu, s, off);
    return s;
}

__global__ void __launch_bounds__(64)
gat_agg_kernel(const float* __restrict__ att, const float* __restrict__ bias,
               const float* __restrict__ gamma, const float* __restrict__ beta,
               float* __restrict__ ext_out, int write_ext) {
    int node = blockIdx.x;
    int warp = threadIdx.x >> 5;                      // 0..1
    int lane = threadIdx.x & 31;
    int c0   = (warp * 2 + (lane >> 4)) * 64 + (lane & 15) * 4;

    float4 xrv  = *(const float4*)&g_xr[(size_t)node * DD + c0];
    float4 attv = *(const float4*)&att[c0];

    // self loop initializes running softmax state (p = 1)
    float4 xs = *(const float4*)&g_xl[(size_t)node * DD + c0];
    float4 a = lrelu4(make_float4(xs.x + xrv.x, xs.y + xrv.y,
                                  xs.z + xrv.z, xs.w + xrv.w));
    float m = segred16(dot4(a, attv));
    float lsum = 1.f;
    float4 acc = xs;

    int e   = g_rowptr[node];
    int end = g_rowptr[node + 1];

    // ---- full 8-wide batches (unmasked hot path) ----
    for (; e + 8 <= end; e += 8) {
        int idx[8];
#pragma unroll
        for (int j = 0; j < 8; j++) idx[j] = g_col[e + j];
        float4 xv[8];
#pragma unroll
        for (int j = 0; j < 8; j++)
            xv[j] = *(const float4*)&g_xl[(size_t)idx[j] * DD + c0];
        float sv[8];
#pragma unroll
        for (int j = 0; j < 8; j++) {
            float4 aj = lrelu4(make_float4(xv[j].x + xrv.x, xv[j].y + xrv.y,
                                           xv[j].z + xrv.z, xv[j].w + xrv.w));
            sv[j] = dot4(aj, attv);
        }
#pragma unroll
        for (int off = 8; off; off >>= 1)
#pragma unroll
            for (int j = 0; j < 8; j++)
                sv[j] += __shfl_xor_sync(0xffffffffu, sv[j], off);
        float nm = m;
#pragma unroll
        for (int j = 0; j < 8; j++) nm = fmaxf(nm, sv[j]);
        float sc = __expf(m - nm);
        float p[8];
#pragma unroll
        for (int j = 0; j < 8; j++) p[j] = __expf(sv[j] - nm);
        acc.x *= sc; acc.y *= sc; acc.z *= sc; acc.w *= sc;
        lsum *= sc;
#pragma unroll
        for (int j = 0; j < 8; j++) {
            acc.x += p[j] * xv[j].x;
            acc.y += p[j] * xv[j].y;
            acc.z += p[j] * xv[j].z;
            acc.w += p[j] * xv[j].w;
            lsum += p[j];
        }
        m = nm;
    }

    // ---- one masked batch for the remainder (1..7 edges) ----
    if (e < end) {
        int cnt = end - e;
        int idx[8];
#pragma unroll
        for (int j = 0; j < 8; j++)
            idx[j] = g_col[e + ((j < cnt) ? j : 0)];
        float4 xv[8];
#pragma unroll
        for (int j = 0; j < 8; j++)
            xv[j] = *(const float4*)&g_xl[(size_t)idx[j] * DD + c0];
        float sv[8];
#pragma unroll
        for (int j = 0; j < 8; j++) {
            float4 aj = lrelu4(make_float4(xv[j].x + xrv.x, xv[j].y + xrv.y,
                                           xv[j].z + xrv.z, xv[j].w + xrv.w));
            sv[j] = dot4(aj, attv);
        }
#pragma unroll
        for (int off = 8; off; off >>= 1)
#pragma unroll
            for (int j = 0; j < 8; j++)
                sv[j] += __shfl_xor_sync(0xffffffffu, sv[j], off);
#pragma unroll
        for (int j = 0; j < 8; j++)
            if (j >= cnt) sv[j] = -1e30f;
        float nm = m;
#pragma unroll
        for (int j = 0; j < 8; j++) nm = fmaxf(nm, sv[j]);
        float sc = __expf(m - nm);
        float p[8];
#pragma unroll
        for (int j = 0; j < 8; j++) p[j] = __expf(sv[j] - nm);
        acc.x *= sc; acc.y *= sc; acc.z *= sc; acc.w *= sc;
        lsum *= sc;
#pragma unroll
        for (int j = 0; j < 8; j++) {
            acc.x += p[j] * xv[j].x;
            acc.y += p[j] * xv[j].y;
            acc.z += p[j] * xv[j].z;
            acc.w += p[j] * xv[j].w;
            lsum += p[j];
        }
        m = nm;
    }

    float inv_l = 1.0f / lsum;
    float4 ox4;
    ox4.x = acc.x * inv_l + bias[c0];
    ox4.y = acc.y * inv_l + bias[c0 + 1];
    ox4.z = acc.z * inv_l + bias[c0 + 2];
    ox4.w = acc.w * inv_l + bias[c0 + 3];

    float s1r = ox4.x + ox4.y + ox4.z + ox4.w;
    float s2r = ox4.x * ox4.x + ox4.y * ox4.y + ox4.z * ox4.z + ox4.w * ox4.w;
#pragma unroll
    for (int off = 16; off; off >>= 1) {
        s1r += __shfl_xor_sync(0xffffffffu, s1r, off);
        s2r += __shfl_xor_sync(0xffffffffu, s2r, off);
    }
    __shared__ float sh1[2], sh2[2];
    if (lane == 0) { sh1[warp] = s1r; sh2[warp] = s2r; }
    __syncthreads();
    s1r = sh1[0] + sh1[1];
    s2r = sh2[0] + sh2[1];

    float mean = s1r * (1.0f / DD);
    float var  = s2r * (1.0f / DD) - mean * mean;
    float rinv = rsqrtf(var + 1e-5f);

    float o0 = fmaxf((ox4.x - mean) * rinv * gamma[c0]     + beta[c0],     0.f);
    float o1 = fmaxf((ox4.y - mean) * rinv * gamma[c0 + 1] + beta[c0 + 1], 0.f);
    float o2 = fmaxf((ox4.z - mean) * rinv * gamma[c0 + 2] + beta[c0 + 2], 0.f);
    float o3 = fmaxf((ox4.w - mean) * rinv * gamma[c0 + 3] + beta[c0 + 3], 0.f);

    if (write_ext) {
        *(float4*)&ext_out[(size_t)node * DD + c0] = make_float4(o0, o1, o2, o3);
    } else {
        __nv_bfloat16 h0 = __float2bfloat16_rn(o0);
        __nv_bfloat16 h1 = __float2bfloat16_rn(o1);
        __nv_bfloat16 h2 = __float2bfloat16_rn(o2);
        __nv_bfloat16 h3 = __float2bfloat16_rn(o3);
        __nv_bfloat16 l0 = __float2bfloat16_rn(o0 - __bfloat162float(h0));
        __nv_bfloat16 l1 = __float2bfloat16_rn(o1 - __bfloat162float(h1));
        __nv_bfloat16 l2 = __float2bfloat16_rn(o2 - __bfloat162float(h2));
        __nv_bfloat16 l3 = __float2bfloat16_rn(o3 - __bfloat162float(h3));
        uint2 hp, lp;
        hp.x = (uint32_t)__bfloat16_as_ushort(h0) |
               ((uint32_t)__bfloat16_as_ushort(h1) << 16);
        hp.y = (uint32_t)__bfloat16_as_ushort(h2) |
               ((uint32_t)__bfloat16_as_ushort(h3) << 16);
        lp.x = (uint32_t)__bfloat16_as_ushort(l0) |
               ((uint32_t)__bfloat16_as_ushort(l1) << 16);
        lp.y = (uint32_t)__bfloat16_as_ushort(l2) |
               ((uint32_t)__bfloat16_as_ushort(l3) << 16);
        *(uint2*)&g_Ah[(size_t)node * DD + c0] = hp;
        *(uint2*)&g_Al[(size_t)node * DD + c0] = lp;
    }
}

// ---------------- launch ---------------------------------------------------
extern "C" void kernel_launch(void* const* d_in, const int* in_sizes, int n_in,
                              void* d_out, int out_size) {
    const float* x  = (const float*)d_in[0];
    const int*   ei = (const int*)d_in[1];
    int E = in_sizes[1] / 2;          // 320000
    int N = in_sizes[0] / DD;         // 20000
    float* out = (float*)d_out;

    static int inited = 0;
    static cudaStream_t s2;
    static cudaEvent_t evFork, evJoin;
    if (!inited) {
        cudaFuncSetAttribute(gemm_kernel,
                             cudaFuncAttributeMaxDynamicSharedMemorySize,
                             GEMM_SMEM);
        cudaStreamCreateWithFlags(&s2, cudaStreamNonBlocking);
        cudaEventCreateWithFlags(&evFork, cudaEventDisableTiming);
        cudaEventCreateWithFlags(&evJoin, cudaEventDisableTiming);
        inited = 1;
    }
    dim3 ggrid(4, (N + 63) / 64);
    int total4 = N * DD / 4;

    // Fork: CSR chain (hist->scan->scatter) on s2, concurrent with the
    // dense chain (convert->prep->gemm0) on the main stream. Join before agg0.
    cudaEventRecord(evFork, 0);
    cudaStreamWaitEvent(s2, evFork, 0);

    convert_x_kernel<<<(total4 + 255) / 256, 256>>>(x, total4);       // idx 0
    prep_all_kernel<<<dim3(8, 8, 8), dim3(32, 8)>>>(                  // idx 1
        (const float*)d_in[2],  (const float*)d_in[3],
        (const float*)d_in[8],  (const float*)d_in[9],
        (const float*)d_in[14], (const float*)d_in[15],
        (const float*)d_in[20], (const float*)d_in[21]);
    hist_kernel<<<(E + 255) / 256, 256, 0, s2>>>(ei, E);              // idx 2
    gemm_kernel<<<ggrid, 256, GEMM_SMEM>>>(N, 0);                     // idx 3 <- profiled
    scan_kernel<<<1, 1024, 0, s2>>>(N);                               // idx 4
    scatter_kernel<<<(E + 255) / 256, 256, 0, s2>>>(ei, E);           // idx 5

    cudaEventRecord(evJoin, s2);
    cudaStreamWaitEvent(0, evJoin, 0);

    for (int layer = 0; layer < 4; layer++) {
        const float* att = (const float*)d_in[2 + 6 * layer + 2];
        const float* b   = (const float*)d_in[2 + 6 * layer + 3];
        const float* g   = (const float*)d_in[2 + 6 * layer + 4];
        const float* be  = (const float*)d_in[2 + 6 * layer + 5];

        if (layer > 0)
            gemm_kernel<<<ggrid, 256, GEMM_SMEM>>>(N, layer);
        gat_agg_kernel<<<N, 64>>>(att, b, g, be, out, layer == 3);
    }
}